// round 2
// baseline (speedup 1.0000x reference)
#include <cuda_runtime.h>

#define NUM_P 4
#define NUM_B 256
#define NUM_N 65536
#define NUM_D 256
#define KTOP  10
#define SCALE_F 10.0f

#define BM 64
#define BN 128
#define BK 16
#define TILES_PER_CHUNK 4
#define CHUNK_N (BN * TILES_PER_CHUNK)   // 512
#define NCHUNKS (NUM_N / CHUNK_N)        // 128
#define DT_LD 132

#define INF_F __int_as_float(0x7f800000)

struct Partial {
    float v[KTOP];
    int   id[KTOP];
    float m;
    float s;
};

// static scratch (no allocations allowed)
__device__ Partial g_part[NUM_P * NUM_B * NCHUNKS];   // ~11.5 MB
__device__ float   g_cnorm[NUM_P * NUM_N];            // 1 MB
__device__ float   g_rowdiff[NUM_P * NUM_B];          // 4 KB

// ---------------------------------------------------------------------------
// helpers
// ---------------------------------------------------------------------------
__device__ __forceinline__ void topk_insert(float v, int idx, float* tv, int* ti) {
    if (v < tv[KTOP - 1]) {
        tv[KTOP - 1] = v; ti[KTOP - 1] = idx;
        #pragma unroll
        for (int i = KTOP - 1; i > 0; --i) {
            if (tv[i] < tv[i - 1]) {
                float t = tv[i]; tv[i] = tv[i - 1]; tv[i - 1] = t;
                int   u = ti[i]; ti[i] = ti[i - 1]; ti[i - 1] = u;
            }
        }
    }
}

// running logsumexp of exp(-SCALE*d): state (m = min d, s = sum exp(-SCALE*(d-m)))
__device__ __forceinline__ void lse_merge(float& m, float& s, float m2, float s2) {
    if (m2 < m) {
        s = s * expf(SCALE_F * (m2 - m)) + s2;
        m = m2;
    } else {
        s = s + s2 * expf(SCALE_F * (m - m2));
    }
}

// ---------------------------------------------------------------------------
// kernel 1: per-center squared norms
// ---------------------------------------------------------------------------
__global__ void cnorm_kernel(const float* __restrict__ centers) {
    int warp = (blockIdx.x * blockDim.x + threadIdx.x) >> 5;
    int lane = threadIdx.x & 31;
    if (warp >= NUM_P * NUM_N) return;
    const float4* row = (const float4*)(centers + (size_t)warp * NUM_D);
    float s = 0.0f;
    #pragma unroll
    for (int i = 0; i < 2; ++i) {
        float4 v = row[lane + i * 32];
        s += v.x * v.x + v.y * v.y + v.z * v.z + v.w * v.w;
    }
    #pragma unroll
    for (int o = 16; o; o >>= 1) s += __shfl_xor_sync(0xffffffffu, s, o);
    if (lane == 0) g_cnorm[warp] = s;
}

// ---------------------------------------------------------------------------
// kernel 2: fused distance-GEMM + per-row top-K + online LSE -> partials
//   grid: (NCHUNKS, NUM_B/BM, NUM_P), 256 threads
// ---------------------------------------------------------------------------
__global__ __launch_bounds__(256, 2)
void main_kernel(const float* __restrict__ feature,
                 const float* __restrict__ centers,
                 const int*   __restrict__ position)
{
    __shared__ float As[BK][BM];        // 4 KB
    __shared__ float Bs[BK][BN];        // 8 KB
    __shared__ float dt[BM * DT_LD];    // 33 KB (also overlaid by merge arrays)
    __shared__ float s_cn[BN];

    const int p     = blockIdx.z;
    const int rg    = blockIdx.y;
    const int chunk = blockIdx.x;
    const int b0    = rg * BM;
    const int tid   = threadIdx.x;
    const int ty    = tid >> 4;     // 0..15 (4 rows each)
    const int tx    = tid & 15;     // 0..15 (8 cols each)
    const int srow  = tid >> 2;     // 0..63 scan row
    const int sq    = tid & 3;      // quarter of the 128 cols

    const int mypos = position[b0 + srow];

    float tv[KTOP]; int ti[KTOP];
    #pragma unroll
    for (int i = 0; i < KTOP; ++i) { tv[i] = INF_F; ti[i] = -1; }
    float lm = INF_F, ls = 0.0f;

    const float* fbase = feature + ((size_t)p * NUM_B + b0) * NUM_D;

    for (int t = 0; t < TILES_PER_CHUNK; ++t) {
        const int n0 = chunk * CHUNK_N + t * BN;
        const float* cbase = centers + ((size_t)p * NUM_N + n0) * NUM_D;

        float acc[4][8];
        #pragma unroll
        for (int i = 0; i < 4; ++i)
            #pragma unroll
            for (int j = 0; j < 8; ++j) acc[i][j] = 0.0f;

        for (int kt = 0; kt < NUM_D; kt += BK) {
            __syncthreads();   // guards As/Bs/dt reuse
            {   // A tile: 64 rows x 16 k (float4 per thread)
                int r = tid >> 2, kq = tid & 3;
                float4 v = *(const float4*)(fbase + (size_t)r * NUM_D + kt + kq * 4);
                As[kq * 4 + 0][r] = v.x; As[kq * 4 + 1][r] = v.y;
                As[kq * 4 + 2][r] = v.z; As[kq * 4 + 3][r] = v.w;
            }
            #pragma unroll
            for (int i = 0; i < 2; ++i) {  // B tile: 128 rows x 16 k
                int vt = tid + i * 256;
                int c = vt >> 2, kq = vt & 3;
                float4 v = *(const float4*)(cbase + (size_t)c * NUM_D + kt + kq * 4);
                Bs[kq * 4 + 0][c] = v.x; Bs[kq * 4 + 1][c] = v.y;
                Bs[kq * 4 + 2][c] = v.z; Bs[kq * 4 + 3][c] = v.w;
            }
            if (kt == 0 && tid < BN)
                s_cn[tid] = g_cnorm[(size_t)p * NUM_N + n0 + tid];
            __syncthreads();
            #pragma unroll
            for (int k = 0; k < BK; ++k) {
                float4 a0 = *(const float4*)&As[k][ty * 4];
                float4 q0 = *(const float4*)&Bs[k][tx * 8];
                float4 q1 = *(const float4*)&Bs[k][tx * 8 + 4];
                float a[4] = {a0.x, a0.y, a0.z, a0.w};
                float bb[8] = {q0.x, q0.y, q0.z, q0.w, q1.x, q1.y, q1.z, q1.w};
                #pragma unroll
                for (int i = 0; i < 4; ++i)
                    #pragma unroll
                    for (int j = 0; j < 8; ++j) acc[i][j] += a[i] * bb[j];
            }
        }
        __syncthreads();   // all smem reads of As/Bs done before dt overwrite
        #pragma unroll
        for (int i = 0; i < 4; ++i) {
            int r = ty * 4 + i;
            #pragma unroll
            for (int j = 0; j < 8; ++j) {
                int c = tx * 8 + j;
                dt[r * DT_LD + c] = s_cn[c] - 2.0f * acc[i][j];
            }
        }
        __syncthreads();
        // per-row streaming scan (4 threads/row, interleaved cols)
        for (int cc = 0; cc < 32; ++cc) {
            int c  = sq + 4 * cc;
            int gn = n0 + c;
            float d = dt[srow * DT_LD + c];
            if (gn == mypos) continue;         // masked position -> inf in reference
            lse_merge(lm, ls, d, 1.0f);
            topk_insert(d, gn, tv, ti);
        }
    }
    __syncthreads();   // scan reads of dt finished before overlay writes

    // merge the 4 per-row thread states via smem overlay on dt
    float* mv = dt;                         // 256*10 floats
    int*   mi = (int*)(dt + 2560);          // 256*10 ints
    float* mm = dt + 5120;                  // 256
    float* ms = dt + 5376;                  // 256
    #pragma unroll
    for (int i = 0; i < KTOP; ++i) { mv[tid * KTOP + i] = tv[i]; mi[tid * KTOP + i] = ti[i]; }
    mm[tid] = lm; ms[tid] = ls;
    __syncthreads();

    if (sq == 0) {
        #pragma unroll
        for (int tt = 1; tt < 4; ++tt) {
            int ot = tid + tt;
            for (int i = 0; i < KTOP; ++i) {
                float v = mv[ot * KTOP + i];
                if (v >= tv[KTOP - 1]) break;  // sorted ascending -> early out
                topk_insert(v, mi[ot * KTOP + i], tv, ti);
            }
            lse_merge(lm, ls, mm[ot], ms[ot]);
        }
        Partial* pp = &g_part[(((size_t)p * NUM_B) + b0 + srow) * NCHUNKS + chunk];
        #pragma unroll
        for (int i = 0; i < KTOP; ++i) { pp->v[i] = tv[i]; pp->id[i] = ti[i]; }
        pp->m = lm; pp->s = ls;
    }
}

// ---------------------------------------------------------------------------
// kernel 3: per-row reduction of NCHUNKS partials -> pos_vid + (y - x)
//   grid: NUM_P*NUM_B blocks, 128 threads (== NCHUNKS)
// ---------------------------------------------------------------------------
__global__ __launch_bounds__(128)
void reduce_kernel(const int* __restrict__ position,
                   const int* __restrict__ mem_pid,
                   float*     __restrict__ out)
{
    __shared__ float cv[NCHUNKS * KTOP];
    __shared__ int   ci[NCHUNKS * KTOP];
    __shared__ float rm[128], rs[128];
    __shared__ float redv[128];
    __shared__ int   redp[128];

    const int row = blockIdx.x;         // p*256 + b
    const int b   = row & 255;
    const int t   = threadIdx.x;

    const Partial* pp = &g_part[(size_t)row * NCHUNKS + t];
    #pragma unroll
    for (int i = 0; i < KTOP; ++i) { cv[t * KTOP + i] = pp->v[i]; ci[t * KTOP + i] = pp->id[i]; }
    rm[t] = pp->m; rs[t] = pp->s;
    __syncthreads();

    // LSE tree reduce over 128 partials
    for (int off = 64; off; off >>= 1) {
        if (t < off) {
            float m1 = rm[t], s1 = rs[t];
            lse_merge(m1, s1, rm[t + off], rs[t + off]);
            rm[t] = m1; rs[t] = s1;
        }
        __syncthreads();
    }

    // global top-10 via 10 rounds of block argmin over 1280 candidates
    float selv[KTOP]; int seli[KTOP];
    for (int r = 0; r < KTOP; ++r) {
        float bv = INF_F; int bp = -1;
        for (int i = t; i < NCHUNKS * KTOP; i += 128) {
            float v = cv[i];
            if (v < bv) { bv = v; bp = i; }
        }
        redv[t] = bv; redp[t] = bp;
        __syncthreads();
        for (int off = 64; off; off >>= 1) {
            if (t < off && redv[t + off] < redv[t]) {
                redv[t] = redv[t + off]; redp[t] = redp[t + off];
            }
            __syncthreads();
        }
        int wp = redp[0];
        selv[r] = redv[0];
        seli[r] = ci[wp];
        if (t == 0) cv[wp] = INF_F;
        __syncthreads();
    }

    if (t == 0) {
        float d0 = selv[0];
        float xrel = 0.0f;
        #pragma unroll
        for (int i = 0; i < KTOP; ++i) xrel += expf(-SCALE_F * (selv[i] - d0));
        float y = -SCALE_F * rm[0] + logf(rs[0]);
        float x = -SCALE_F * d0   + logf(xrel);
        g_rowdiff[row] = y - x;

        int pos = position[b];
        #pragma unroll
        for (int i = 0; i < KTOP; ++i) {
            int gi = seli[i];
            int fi = gi - (gi > pos ? 1 : 0);
            out[1 + row * KTOP + i] = (float)mem_pid[fi];
        }
    }
}

// ---------------------------------------------------------------------------
// kernel 4: deterministic loss finalize
// ---------------------------------------------------------------------------
__global__ void finalize_kernel(float* __restrict__ out) {
    __shared__ float lp[NUM_P];
    int t = threadIdx.x, w = t >> 5, lane = t & 31;
    if (w < NUM_P) {
        float s = 0.0f;
        for (int b = lane; b < NUM_B; b += 32) s += g_rowdiff[w * NUM_B + b];
        #pragma unroll
        for (int o = 16; o; o >>= 1) s += __shfl_xor_sync(0xffffffffu, s, o);
        if (lane == 0) lp[w] = s / (float)NUM_B;
    }
    __syncthreads();
    if (t == 0) {
        float L = 0.0f;
        #pragma unroll
        for (int p = 0; p < NUM_P; ++p) {
            float v = lp[p];
            if (!isnan(v)) L += v;
        }
        out[0] = L / (float)NUM_P;
    }
}

// ---------------------------------------------------------------------------
extern "C" void kernel_launch(void* const* d_in, const int* in_sizes, int n_in,
                              void* d_out, int out_size) {
    const float* feature  = (const float*)d_in[0];   // (P,B,D) f32
    const float* centers  = (const float*)d_in[1];   // (P,N,D) f32
    const int*   position = (const int*)  d_in[2];   // (B,)
    // d_in[3] camid, d_in[4] mem_camid: unused by reference
    const int*   mem_pid  = (const int*)  d_in[5];   // (N,)
    float* out = (float*)d_out;                       // [0]=loss, [1..]=pos_vid

    cnorm_kernel<<<(NUM_P * NUM_N) / 8, 256>>>(centers);
    main_kernel<<<dim3(NCHUNKS, NUM_B / BM, NUM_P), 256>>>(feature, centers, position);
    reduce_kernel<<<NUM_P * NUM_B, 128>>>(position, mem_pid, out);
    finalize_kernel<<<1, 128>>>(out);
}